// round 6
// baseline (speedup 1.0000x reference)
#include <cuda_runtime.h>
#include <cuda_fp16.h>

#define NN   50000
#define NE   800000
#define NEDG (NE + NN)
#define NG   512
#define CH   64
#define NB   ((NN + 255) / 256)      // 196 scan blocks
#define FULL 0xffffffffu
#define GEMM_BLKS 592
#define HIST_BLKS ((NE + 255) / 256) // 3125

// ---------------- scratch (device globals; no allocations allowed) ----------
__device__ __half2 g_h[NN * 32];   // per-layer h = X @ W  (fp16, row = 32 half2)
__device__ float2 g_out[NN * 32];  // per-layer aggregated + elu output (fp32)
__device__ float g_as[NN];
__device__ float g_ad[NN];
__device__ int   g_deg[NN];        // edge histogram; zeroed by k_scan_a (restore)
__device__ int   g_off[NN + 1];    // BLOCK-LOCAL exclusive offsets (+g_bpre = absolute)
__device__ int   g_cur[NN];        // relative cursors; zeroed by k_front
__device__ int   g_csr[NEDG];      // src node per dst-sorted edge
__device__ float g_pool[NG * CH];  // zeroed by k_front
__device__ float g_cnt[NG];        // zeroed by k_front
__device__ int   g_bsum[NB];
__device__ int   g_bpre[NB];
__device__ int   g_tick;           // scan ticket; self-resetting
__device__ int   g_tick2;          // pool ticket; self-resetting

// element-indexed index load, dtype-dispatched, clamped for safety
__device__ __forceinline__ int ld_idx(const void* __restrict__ p, long long i, int is32, int lim) {
    long long v = is32 ? (long long)((const int*)p)[i] : ((const long long*)p)[i];
    if (v < 0) v = 0;
    if (v >= lim) v = lim - 1;
    return (int)v;
}

// per-block dtype detection (first 64 values of ei must be < NN if int64)
__device__ __forceinline__ int block_detect(const void* __restrict__ ei) {
    __shared__ int s_is32;
    if (threadIdx.x < 32) {
        const long long* p = (const long long*)ei;
        long long v0 = p[threadIdx.x];
        long long v1 = p[threadIdx.x + 32];
        int bad = (v0 < 0 || v0 >= NN || v1 < 0 || v1 >= NN);
        unsigned any = __ballot_sync(FULL, bad);
        if (threadIdx.x == 0) s_is32 = (any != 0u) ? 1 : 0;
    }
    __syncthreads();
    return s_is32;
}

// ---------------- shared gemm body (warp per node) --------------------------
// lane owns output cols (2*lane, 2*lane+1); h stored fp16, as/ad fp32
__device__ __forceinline__ void gemm_body(const float2* __restrict__ Xp,
                                          const float* __restrict__ W,
                                          const float* __restrict__ a_src,
                                          const float* __restrict__ a_dst,
                                          float2* Ws2, float2* as2, float2* ad2) {
    const int tid = threadIdx.x;
    for (int i = tid; i < CH * 32; i += blockDim.x) Ws2[i] = ((const float2*)W)[i];
    if (tid < 32) {
        as2[tid] = ((const float2*)a_src)[tid];
        ad2[tid] = ((const float2*)a_dst)[tid];
    }
    __syncthreads();

    const int lane = tid & 31;
    const int warp = (blockIdx.x * blockDim.x + tid) >> 5;
    const int nwarps = GEMM_BLKS * 256 / 32;

    for (int i = warp; i < NN; i += nwarps) {
        float2 xv = Xp[i * 32 + lane];
        float acc0 = 0.f, acc1 = 0.f;
        #pragma unroll
        for (int k = 0; k < 32; k++) {
            float xa = __shfl_sync(FULL, xv.x, k);
            float xb = __shfl_sync(FULL, xv.y, k);
            float2 wa = Ws2[(2 * k) * 32 + lane];
            float2 wb = Ws2[(2 * k + 1) * 32 + lane];
            acc0 = fmaf(xa, wa.x, acc0);
            acc1 = fmaf(xa, wa.y, acc1);
            acc0 = fmaf(xb, wb.x, acc0);
            acc1 = fmaf(xb, wb.y, acc1);
        }
        g_h[i * 32 + lane] = __floats2half2_rn(acc0, acc1);

        float2 av = as2[lane], dv = ad2[lane];
        float ps = acc0 * av.x + acc1 * av.y;
        float pd = acc0 * dv.x + acc1 * dv.y;
        #pragma unroll
        for (int o = 16; o; o >>= 1) {
            ps += __shfl_xor_sync(FULL, ps, o);
            pd += __shfl_xor_sync(FULL, pd, o);
        }
        if (lane == 0) { g_as[i] = ps; g_ad[i] = pd; }
    }
}

// ---------------- fused front: gemm1 (blocks<592) + hist/zero (rest) --------
__global__ void k_front(const float2* __restrict__ X2,
                        const float* __restrict__ W,
                        const float* __restrict__ a_src,
                        const float* __restrict__ a_dst,
                        const void* __restrict__ ei) {
    __shared__ float2 smem[CH * 32 + 64];
    if (blockIdx.x < GEMM_BLKS) {
        gemm_body(X2, W, a_src, a_dst, smem, smem + CH * 32, smem + CH * 32 + 32);
        return;
    }
    int is32 = block_detect(ei);
    int t = (blockIdx.x - GEMM_BLKS) * 256 + threadIdx.x;
    if (t < NG * CH) g_pool[t] = 0.0f;
    if (t < NG) g_cnt[t] = 0.0f;
    if (t < NN) g_cur[t] = 0;
    if (t < NE) {
        int d = ld_idx(ei, (long long)NE + t, is32, NN);
        atomicAdd(&g_deg[d], 1);
    }
}

// ---------------- scan phase A + fused phase B (last-block ticket) ----------
__global__ void k_scan_a() {
    const int t = threadIdx.x;
    const int i = blockIdx.x * 256 + t;
    const int lane = t & 31, wid = t >> 5;
    int d = 0;
    if (i < NN) {
        d = g_deg[i] + 1;      // +1 = self loop
        g_deg[i] = 0;          // restore for next launch
    }
    int v = d;
    #pragma unroll
    for (int o = 1; o < 32; o <<= 1) {
        int u = __shfl_up_sync(FULL, v, o);
        if (lane >= o) v += u;
    }
    __shared__ int ws[8];
    if (lane == 31) ws[wid] = v;
    __syncthreads();
    if (t < 8) {
        int u = ws[t];
        #pragma unroll
        for (int o = 1; o < 8; o <<= 1) {
            int w2 = __shfl_up_sync(0xffu, u, o);
            if (t >= o) u += w2;
        }
        ws[t] = u;
    }
    __syncthreads();
    int incl = v + (wid ? ws[wid - 1] : 0);
    if (i < NN) g_off[i] = incl - d;            // block-local exclusive
    if (t == 255) g_bsum[blockIdx.x] = incl;

    // ---- last finishing block performs the block-sum scan (phase B) ----
    __threadfence();
    __shared__ int is_last;
    if (t == 0) {
        int old = atomicAdd(&g_tick, 1);
        is_last = (old == (int)gridDim.x - 1);
    }
    __syncthreads();
    if (!is_last) return;
    __threadfence();

    int d2 = (t < NB) ? g_bsum[t] : 0;
    int v2 = d2;
    #pragma unroll
    for (int o = 1; o < 32; o <<= 1) {
        int u = __shfl_up_sync(FULL, v2, o);
        if (lane >= o) v2 += u;
    }
    __shared__ int ws2[8];
    if (lane == 31) ws2[wid] = v2;
    __syncthreads();
    if (t < 8) {
        int u = ws2[t];
        #pragma unroll
        for (int o = 1; o < 8; o <<= 1) {
            int w2 = __shfl_up_sync(0xffu, u, o);
            if (t >= o) u += w2;
        }
        ws2[t] = u;
    }
    __syncthreads();
    int incl2 = v2 + (wid ? ws2[wid - 1] : 0);
    if (t < NB) g_bpre[t] = incl2 - d2;
    if (t == 255) { g_off[NN] = incl2; g_tick = 0; }   // g_off[NN] is absolute
}

// ---------------- scatter edges (incl self loops) into CSR ------------------
__global__ void k_scatter(const void* __restrict__ ei) {
    int is32 = block_detect(ei);
    int t = blockIdx.x * blockDim.x + threadIdx.x;
    if (t >= NEDG) return;
    if (t < NE) {
        int d = ld_idx(ei, (long long)NE + t, is32, NN);
        int s = ld_idx(ei, (long long)t, is32, NN);
        int r = atomicAdd(&g_cur[d], 1);
        g_csr[g_off[d] + g_bpre[d >> 8] + r] = s;
    } else {
        int i = t - NE;
        int r = atomicAdd(&g_cur[i], 1);
        g_csr[g_off[i] + g_bpre[i >> 8] + r] = i;   // self loop
    }
}

// ---------------- standalone gemm (layer 2) ---------------------------------
__global__ void k_gemm2(const float* __restrict__ W,
                        const float* __restrict__ a_src,
                        const float* __restrict__ a_dst) {
    __shared__ float2 smem[CH * 32 + 64];
    gemm_body((const float2*)g_out, W, a_src, a_dst,
              smem, smem + CH * 32, smem + CH * 32 + 32);
}

// ---------------- warp-per-dst: softmax over incoming edges + aggregation ---
__global__ void k_agg(const float* __restrict__ bias) {
    const int w = (blockIdx.x * blockDim.x + threadIdx.x) >> 5;
    const int lane = threadIdx.x & 31;
    if (w >= NN) return;

    const int beg = g_off[w] + g_bpre[w >> 8];
    const int end = (w + 1 < NN) ? (g_off[w + 1] + g_bpre[(w + 1) >> 8]) : g_off[NN];
    const int deg = end - beg;
    const float adi = g_ad[w];

    float accx = 0.f, accy = 0.f;

    if (deg <= 128) {
        // -------- fast path: edge list cached in registers --------
        const int nch = (deg + 31) >> 5;
        int   sn_r[4];
        float l_r[4];
        float m = -1e30f, s = 0.f;
        #pragma unroll
        for (int c = 0; c < 4; c++) {
            int e = beg + c * 32 + lane;
            int valid = (c < nch) && (e < end);
            int sn = 0;
            float l = -1e30f;
            if (valid) {
                sn = g_csr[e];
                l = g_as[sn] + adi;
                l = (l >= 0.f) ? l : 0.2f * l;
            }
            sn_r[c] = sn;
            l_r[c]  = l;
            float mn = fmaxf(m, l);
            s = s * __expf(m - mn) + (valid ? __expf(l - mn) : 0.f);
            m = mn;
        }
        #pragma unroll
        for (int o = 16; o; o >>= 1) {
            float m2 = __shfl_xor_sync(FULL, m, o);
            float s2 = __shfl_xor_sync(FULL, s, o);
            float M = fmaxf(m, m2);
            s = s * __expf(m - M) + s2 * __expf(m2 - M);
            m = M;
        }
        const float inv = 1.0f / s;

        #pragma unroll
        for (int c = 0; c < 4; c++) {
            if (c >= nch) continue;
            int base = beg + c * 32;
            int n = min(32, end - base);
            float wgt = __expf(l_r[c] - m) * inv;   // invalid lanes -> 0
            int sn = sn_r[c];
            int j = 0;
            for (; j + 4 <= n; j += 4) {
                int   s0 = __shfl_sync(FULL, sn, j);
                int   s1 = __shfl_sync(FULL, sn, j + 1);
                int   s2 = __shfl_sync(FULL, sn, j + 2);
                int   s3 = __shfl_sync(FULL, sn, j + 3);
                float w0 = __shfl_sync(FULL, wgt, j);
                float w1 = __shfl_sync(FULL, wgt, j + 1);
                float w2 = __shfl_sync(FULL, wgt, j + 2);
                float w3 = __shfl_sync(FULL, wgt, j + 3);
                float2 v0 = __half22float2(g_h[s0 * 32 + lane]);
                float2 v1 = __half22float2(g_h[s1 * 32 + lane]);
                float2 v2 = __half22float2(g_h[s2 * 32 + lane]);
                float2 v3 = __half22float2(g_h[s3 * 32 + lane]);
                accx = fmaf(w0, v0.x, accx);
                accy = fmaf(w0, v0.y, accy);
                accx = fmaf(w1, v1.x, accx);
                accy = fmaf(w1, v1.y, accy);
                accx = fmaf(w2, v2.x, accx);
                accy = fmaf(w2, v2.y, accy);
                accx = fmaf(w3, v3.x, accx);
                accy = fmaf(w3, v3.y, accy);
            }
            for (; j < n; j++) {
                int   sj = __shfl_sync(FULL, sn, j);
                float wj = __shfl_sync(FULL, wgt, j);
                float2 v = __half22float2(g_h[sj * 32 + lane]);
                accx = fmaf(wj, v.x, accx);
                accy = fmaf(wj, v.y, accy);
            }
        }
    } else {
        // -------- fallback: recompute path (arbitrary degree) --------
        float m = -1e30f, s = 0.f;
        for (int e = beg + lane; e < end; e += 32) {
            int sn = g_csr[e];
            float l = g_as[sn] + adi;
            l = (l >= 0.f) ? l : 0.2f * l;
            float mn = fmaxf(m, l);
            s = s * __expf(m - mn) + __expf(l - mn);
            m = mn;
        }
        #pragma unroll
        for (int o = 16; o; o >>= 1) {
            float m2 = __shfl_xor_sync(FULL, m, o);
            float s2 = __shfl_xor_sync(FULL, s, o);
            float M = fmaxf(m, m2);
            s = s * __expf(m - M) + s2 * __expf(m2 - M);
            m = M;
        }
        const float inv = 1.0f / s;

        for (int base = beg; base < end; base += 32) {
            int n = min(32, end - base);
            int sn = 0;
            float wgt = 0.f;
            if (lane < n) {
                sn = g_csr[base + lane];
                float l = g_as[sn] + adi;
                l = (l >= 0.f) ? l : 0.2f * l;
                wgt = __expf(l - m) * inv;
            }
            for (int j = 0; j < n; j++) {
                int   sj = __shfl_sync(FULL, sn, j);
                float wj = __shfl_sync(FULL, wgt, j);
                float2 v = __half22float2(g_h[sj * 32 + lane]);
                accx = fmaf(wj, v.x, accx);
                accy = fmaf(wj, v.y, accy);
            }
        }
    }

    float2 bv = ((const float2*)bias)[lane];
    accx += bv.x;
    accy += bv.y;
    accx = (accx > 0.f) ? accx : expm1f(accx);   // elu
    accy = (accy > 0.f) ? accy : expm1f(accy);
    g_out[w * 32 + lane] = make_float2(accx, accy);
}

// ---------------- global mean pool (warp per 8-node run) + fused divide -----
#define PNODES 8
#define NGRP   ((NN + PNODES - 1) / PNODES)
__global__ void k_pool(const void* __restrict__ batch,
                       const void* __restrict__ ei,
                       float* __restrict__ dout) {
    int is32 = block_detect(ei);
    const int wid = (blockIdx.x * blockDim.x + threadIdx.x) >> 5;
    const int lane = threadIdx.x & 31;

    if (wid < NGRP) {
        const int i0 = wid * PNODES;
        int b = 0;
        if (lane < PNODES && i0 + lane < NN) b = ld_idx(batch, i0 + lane, is32, NG);

        int gprev = __shfl_sync(FULL, b, 0);
        float ax = 0.f, ay = 0.f, cnt = 0.f;
        #pragma unroll
        for (int k = 0; k < PNODES; k++) {
            int i = i0 + k;
            if (i >= NN) break;
            int g = __shfl_sync(FULL, b, k);
            if (g != gprev) {
                atomicAdd(&g_pool[gprev * CH + 2 * lane], ax);
                atomicAdd(&g_pool[gprev * CH + 2 * lane + 1], ay);
                if (lane == 0) atomicAdd(&g_cnt[gprev], cnt);
                ax = 0.f; ay = 0.f; cnt = 0.f; gprev = g;
            }
            float2 v = g_out[i * 32 + lane];
            ax += v.x; ay += v.y; cnt += 1.f;
        }
        atomicAdd(&g_pool[gprev * CH + 2 * lane], ax);
        atomicAdd(&g_pool[gprev * CH + 2 * lane + 1], ay);
        if (lane == 0) atomicAdd(&g_cnt[gprev], cnt);
    }

    // ---- last finishing block performs the divide + writeout ----
    __threadfence();
    __shared__ int is_last;
    if (threadIdx.x == 0) {
        int old = atomicAdd(&g_tick2, 1);
        is_last = (old == (int)gridDim.x - 1);
    }
    __syncthreads();
    if (!is_last) return;
    __threadfence();
    for (int t = threadIdx.x; t < NG * CH; t += blockDim.x)
        dout[t] = g_pool[t] * (1.0f / fmaxf(g_cnt[t >> 6], 1.0f));
    if (threadIdx.x == 0) g_tick2 = 0;
}

// ---------------- entry ------------------------------------------------------
extern "C" void kernel_launch(void* const* d_in, const int* in_sizes, int n_in,
                              void* d_out, int out_size) {
    const float* x     = (const float*)d_in[0];
    const void*  ei    = d_in[1];
    const void*  batch = d_in[2];
    const float* W1    = (const float*)d_in[3];
    const float* as1   = (const float*)d_in[4];
    const float* ad1   = (const float*)d_in[5];
    const float* b1    = (const float*)d_in[6];
    const float* W2    = (const float*)d_in[7];
    const float* as2   = (const float*)d_in[8];
    const float* ad2   = (const float*)d_in[9];
    const float* b2    = (const float*)d_in[10];
    float* dout = (float*)d_out;

    // 1: gemm1 + hist + zeroing (independent workloads, one launch)
    k_front<<<GEMM_BLKS + HIST_BLKS, 256>>>((const float2*)x, W1, as1, ad1, ei);
    // 2: degree scan (phase A + fused phase B)
    k_scan_a<<<NB, 256>>>();
    // 3: CSR scatter
    k_scatter<<<(NEDG + 255) / 256, 256>>>(ei);
    // 4: layer-1 attention + aggregation   (ncu profiles this slot)
    k_agg<<<(NN * 32 + 255) / 256, 256>>>(b1);
    // 5: layer-2 gemm (input = g_out)
    k_gemm2<<<GEMM_BLKS, 256>>>(W2, as2, ad2);
    // 6: layer-2 attention + aggregation
    k_agg<<<(NN * 32 + 255) / 256, 256>>>(b2);
    // 7: pool + divide
    k_pool<<<(NGRP * 32 + 255) / 256, 256>>>(batch, ei, dout);
}

// round 7
// speedup vs baseline: 1.1683x; 1.1683x over previous
#include <cuda_runtime.h>
#include <cuda_fp16.h>

#define NN   50000
#define NE   800000
#define NEDG (NE + NN)
#define NG   512
#define CH   64
#define NB   ((NN + 255) / 256)   // 196 scan blocks
#define FULL 0xffffffffu

// ---------------- scratch (device globals; no allocations allowed) ----------
__device__ __half2 g_h[NN * 32];   // per-layer h = X @ W  (fp16, row = 32 half2)
__device__ float2 g_out[NN * 32];  // per-layer aggregated + elu output (fp32)
__device__ float g_as[NN];
__device__ float g_ad[NN];
__device__ int   g_deg[NN];        // zeroed by k_scan_a after use (state restore)
__device__ int   g_off[NN + 1];
__device__ int   g_cur[NN];
__device__ int   g_csr[NEDG];      // src node per dst-sorted edge
__device__ float g_pool[NG * CH];  // zeroed by k_hist each launch
__device__ float g_cnt[NG];        // zeroed by k_hist each launch
__device__ int   g_bsum[NB];
__device__ int   g_bpre[NB];
__device__ int   g_tick;           // scan ticket; self-resetting

// element-indexed index load, dtype-dispatched, clamped for safety
__device__ __forceinline__ int ld_idx(const void* __restrict__ p, long long i, int is32, int lim) {
    long long v = is32 ? (long long)((const int*)p)[i] : ((const long long*)p)[i];
    if (v < 0) v = 0;
    if (v >= lim) v = lim - 1;
    return (int)v;
}

// per-block dtype detection (first 64 values of ei must be < NN if int64)
__device__ __forceinline__ int block_detect(const void* __restrict__ ei) {
    __shared__ int s_is32;
    if (threadIdx.x < 32) {
        const long long* p = (const long long*)ei;
        long long v0 = p[threadIdx.x];
        long long v1 = p[threadIdx.x + 32];
        int bad = (v0 < 0 || v0 >= NN || v1 < 0 || v1 >= NN);
        unsigned any = __ballot_sync(FULL, bad);
        if (threadIdx.x == 0) s_is32 = (any != 0u) ? 1 : 0;
    }
    __syncthreads();
    return s_is32;
}

// ---------------- histogram of dst degrees (+ zero pool accumulators) -------
__global__ void k_hist(const void* __restrict__ ei) {
    int is32 = block_detect(ei);
    int t = blockIdx.x * blockDim.x + threadIdx.x;
    if (t < NG * CH) g_pool[t] = 0.0f;
    if (t < NG) g_cnt[t] = 0.0f;
    if (t >= NE) return;
    int d = ld_idx(ei, (long long)NE + t, is32, NN);
    atomicAdd(&g_deg[d], 1);
}

// ---------------- scan phase A + fused phase B (last-block ticket) ----------
__global__ void k_scan_a() {
    const int t = threadIdx.x;
    const int i = blockIdx.x * 256 + t;
    const int lane = t & 31, wid = t >> 5;
    int d = 0;
    if (i < NN) {
        d = g_deg[i] + 1;      // +1 = self loop
        g_deg[i] = 0;          // restore for next launch
    }
    int v = d;
    #pragma unroll
    for (int o = 1; o < 32; o <<= 1) {
        int u = __shfl_up_sync(FULL, v, o);
        if (lane >= o) v += u;
    }
    __shared__ int ws[8];
    if (lane == 31) ws[wid] = v;
    __syncthreads();
    if (t < 8) {
        int u = ws[t];
        #pragma unroll
        for (int o = 1; o < 8; o <<= 1) {
            int w2 = __shfl_up_sync(0xffu, u, o);
            if (t >= o) u += w2;
        }
        ws[t] = u;
    }
    __syncthreads();
    int incl = v + (wid ? ws[wid - 1] : 0);
    if (i < NN) g_off[i] = incl - d;
    if (t == 255) g_bsum[blockIdx.x] = incl;

    // ---- last finishing block performs the block-sum scan (phase B) ----
    __threadfence();
    __shared__ int is_last;
    if (t == 0) {
        int old = atomicAdd(&g_tick, 1);
        is_last = (old == (int)gridDim.x - 1);
    }
    __syncthreads();
    if (!is_last) return;
    __threadfence();

    int d2 = (t < NB) ? g_bsum[t] : 0;
    int v2 = d2;
    #pragma unroll
    for (int o = 1; o < 32; o <<= 1) {
        int u = __shfl_up_sync(FULL, v2, o);
        if (lane >= o) v2 += u;
    }
    __shared__ int ws2[8];
    if (lane == 31) ws2[wid] = v2;
    __syncthreads();
    if (t < 8) {
        int u = ws2[t];
        #pragma unroll
        for (int o = 1; o < 8; o <<= 1) {
            int w2 = __shfl_up_sync(0xffu, u, o);
            if (t >= o) u += w2;
        }
        ws2[t] = u;
    }
    __syncthreads();
    int incl2 = v2 + (wid ? ws2[wid - 1] : 0);
    if (t < NB) g_bpre[t] = incl2 - d2;
    if (t == 255) { g_off[NN] = incl2; g_tick = 0; }
}

// phase C: add block prefixes, materialize offsets + cursors
__global__ void k_scan_c() {
    int i = blockIdx.x * 256 + threadIdx.x;
    if (i >= NN) return;
    int o = g_off[i] + g_bpre[blockIdx.x];
    g_off[i] = o;
    g_cur[i] = o;
}

// ---------------- scatter edges (incl self loops) into CSR ------------------
__global__ void k_scatter(const void* __restrict__ ei) {
    int is32 = block_detect(ei);
    int t = blockIdx.x * blockDim.x + threadIdx.x;
    if (t >= NEDG) return;
    if (t < NE) {
        int d = ld_idx(ei, (long long)NE + t, is32, NN);
        int s = ld_idx(ei, (long long)t, is32, NN);
        int p = atomicAdd(&g_cur[d], 1);
        g_csr[p] = s;
    } else {
        int i = t - NE;
        int p = atomicAdd(&g_cur[i], 1);
        g_csr[p] = i;                 // self loop
    }
}

// ---------------- h = X @ W; as = h.a_src; ad = h.a_dst  (warp per node) ----
template <bool FIRST>
__global__ void k_gemm(const float2* __restrict__ X2,
                       const float* __restrict__ W,
                       const float* __restrict__ a_src,
                       const float* __restrict__ a_dst) {
    __shared__ float2 Ws2[CH * 32];
    __shared__ float2 as2[32], ad2[32];
    const int tid = threadIdx.x;
    for (int i = tid; i < CH * 32; i += blockDim.x) Ws2[i] = ((const float2*)W)[i];
    if (tid < 32) {
        as2[tid] = ((const float2*)a_src)[tid];
        ad2[tid] = ((const float2*)a_dst)[tid];
    }
    __syncthreads();

    const float2* __restrict__ Xp = FIRST ? X2 : (const float2*)g_out;
    const int lane = tid & 31;
    const int warp = (blockIdx.x * blockDim.x + tid) >> 5;
    const int nwarps = (gridDim.x * blockDim.x) >> 5;

    for (int i = warp; i < NN; i += nwarps) {
        float2 xv = Xp[i * 32 + lane];
        float acc0 = 0.f, acc1 = 0.f;
        #pragma unroll
        for (int k = 0; k < 32; k++) {
            float xa = __shfl_sync(FULL, xv.x, k);
            float xb = __shfl_sync(FULL, xv.y, k);
            float2 wa = Ws2[(2 * k) * 32 + lane];
            float2 wb = Ws2[(2 * k + 1) * 32 + lane];
            acc0 = fmaf(xa, wa.x, acc0);
            acc1 = fmaf(xa, wa.y, acc1);
            acc0 = fmaf(xb, wb.x, acc0);
            acc1 = fmaf(xb, wb.y, acc1);
        }
        g_h[i * 32 + lane] = __floats2half2_rn(acc0, acc1);

        float2 av = as2[lane], dv = ad2[lane];
        float ps = acc0 * av.x + acc1 * av.y;
        float pd = acc0 * dv.x + acc1 * dv.y;
        #pragma unroll
        for (int o = 16; o; o >>= 1) {
            ps += __shfl_xor_sync(FULL, ps, o);
            pd += __shfl_xor_sync(FULL, pd, o);
        }
        if (lane == 0) { g_as[i] = ps; g_ad[i] = pd; }
    }
}

// ---------------- warp-per-dst: softmax + aggregation (2 edges/iter) --------
// pass 2: half-warp hw handles edge j+hw; each lane loads 4 channels (LDG.64)
__device__ __forceinline__ void agg_window(int sn, float wgt, int n,
                                           int hw, int hl, float4& acc) {
    #pragma unroll 4
    for (int j = 0; j < n; j += 2) {
        int idx = j + hw;
        int srcl = min(idx, n - 1);
        int   sj = __shfl_sync(FULL, sn, srcl);
        float wj = __shfl_sync(FULL, wgt, srcl);
        if (idx >= n) wj = 0.f;
        uint2 raw = *reinterpret_cast<const uint2*>(&g_h[sj * 32 + 2 * hl]);
        float2 va = __half22float2(*reinterpret_cast<const __half2*>(&raw.x));
        float2 vb = __half22float2(*reinterpret_cast<const __half2*>(&raw.y));
        acc.x = fmaf(wj, va.x, acc.x);
        acc.y = fmaf(wj, va.y, acc.y);
        acc.z = fmaf(wj, vb.x, acc.z);
        acc.w = fmaf(wj, vb.y, acc.w);
    }
}

__global__ void k_agg(const float* __restrict__ bias) {
    const int w = (blockIdx.x * blockDim.x + threadIdx.x) >> 5;
    const int lane = threadIdx.x & 31;
    if (w >= NN) return;
    const int hw = lane >> 4;     // half-warp id (0/1)
    const int hl = lane & 15;     // lane within half-warp

    const int beg = g_off[w];
    const int end = g_off[w + 1];
    const int deg = end - beg;
    const float adi = g_ad[w];

    float4 acc = make_float4(0.f, 0.f, 0.f, 0.f);

    if (deg <= 128) {
        // -------- fast path: edge list cached in registers --------
        const int nch = (deg + 31) >> 5;
        int   sn_r[4];
        float l_r[4];
        float m = -1e30f, s = 0.f;
        #pragma unroll
        for (int c = 0; c < 4; c++) {
            int e = beg + c * 32 + lane;
            int valid = (c < nch) && (e < end);
            int sn = 0;
            float l = -1e30f;
            if (valid) {
                sn = g_csr[e];
                l = g_as[sn] + adi;
                l = (l >= 0.f) ? l : 0.2f * l;
            }
            sn_r[c] = sn;
            l_r[c]  = l;
            float mn = fmaxf(m, l);
            s = s * __expf(m - mn) + (valid ? __expf(l - mn) : 0.f);
            m = mn;
        }
        #pragma unroll
        for (int o = 16; o; o >>= 1) {
            float m2 = __shfl_xor_sync(FULL, m, o);
            float s2 = __shfl_xor_sync(FULL, s, o);
            float M = fmaxf(m, m2);
            s = s * __expf(m - M) + s2 * __expf(m2 - M);
            m = M;
        }
        const float inv = 1.0f / s;

        #pragma unroll
        for (int c = 0; c < 4; c++) {
            if (c >= nch) break;
            int n = min(32, end - (beg + c * 32));
            float wgt = __expf(l_r[c] - m) * inv;   // invalid lanes -> 0
            agg_window(sn_r[c], wgt, n, hw, hl, acc);
        }
    } else {
        // -------- fallback: recompute path (arbitrary degree) --------
        float m = -1e30f, s = 0.f;
        for (int e = beg + lane; e < end; e += 32) {
            int sn = g_csr[e];
            float l = g_as[sn] + adi;
            l = (l >= 0.f) ? l : 0.2f * l;
            float mn = fmaxf(m, l);
            s = s * __expf(m - mn) + __expf(l - mn);
            m = mn;
        }
        #pragma unroll
        for (int o = 16; o; o >>= 1) {
            float m2 = __shfl_xor_sync(FULL, m, o);
            float s2 = __shfl_xor_sync(FULL, s, o);
            float M = fmaxf(m, m2);
            s = s * __expf(m - M) + s2 * __expf(m2 - M);
            m = M;
        }
        const float inv = 1.0f / s;

        for (int base = beg; base < end; base += 32) {
            int n = min(32, end - base);
            int sn = 0;
            float wgt = 0.f;
            if (lane < n) {
                sn = g_csr[base + lane];
                float l = g_as[sn] + adi;
                l = (l >= 0.f) ? l : 0.2f * l;
                wgt = __expf(l - m) * inv;
            }
            agg_window(sn, wgt, n, hw, hl, acc);
        }
    }

    // combine the two half-warps, then lanes 0-15 write a float4 each
    acc.x += __shfl_xor_sync(FULL, acc.x, 16);
    acc.y += __shfl_xor_sync(FULL, acc.y, 16);
    acc.z += __shfl_xor_sync(FULL, acc.z, 16);
    acc.w += __shfl_xor_sync(FULL, acc.w, 16);

    if (lane < 16) {
        float4 bv = ((const float4*)bias)[hl];
        acc.x += bv.x; acc.y += bv.y; acc.z += bv.z; acc.w += bv.w;
        acc.x = (acc.x > 0.f) ? acc.x : expm1f(acc.x);   // elu
        acc.y = (acc.y > 0.f) ? acc.y : expm1f(acc.y);
        acc.z = (acc.z > 0.f) ? acc.z : expm1f(acc.z);
        acc.w = (acc.w > 0.f) ? acc.w : expm1f(acc.w);
        ((float4*)g_out)[w * 16 + hl] = acc;
    }
}

// ---------------- global mean pool (warp per 8-node run) ---------------------
#define PNODES 8
#define NGRP   ((NN + PNODES - 1) / PNODES)
__global__ void k_pool(const void* __restrict__ batch, const void* __restrict__ ei) {
    int is32 = block_detect(ei);
    const int wid = (blockIdx.x * blockDim.x + threadIdx.x) >> 5;
    const int lane = threadIdx.x & 31;
    if (wid >= NGRP) return;
    const int i0 = wid * PNODES;

    int b = 0;
    if (lane < PNODES && i0 + lane < NN) b = ld_idx(batch, i0 + lane, is32, NG);

    int gprev = __shfl_sync(FULL, b, 0);
    float ax = 0.f, ay = 0.f, cnt = 0.f;
    #pragma unroll
    for (int k = 0; k < PNODES; k++) {
        int i = i0 + k;
        if (i >= NN) break;
        int g = __shfl_sync(FULL, b, k);
        if (g != gprev) {
            atomicAdd(&g_pool[gprev * CH + 2 * lane], ax);
            atomicAdd(&g_pool[gprev * CH + 2 * lane + 1], ay);
            if (lane == 0) atomicAdd(&g_cnt[gprev], cnt);
            ax = 0.f; ay = 0.f; cnt = 0.f; gprev = g;
        }
        float2 v = g_out[i * 32 + lane];
        ax += v.x; ay += v.y; cnt += 1.f;
    }
    atomicAdd(&g_pool[gprev * CH + 2 * lane], ax);
    atomicAdd(&g_pool[gprev * CH + 2 * lane + 1], ay);
    if (lane == 0) atomicAdd(&g_cnt[gprev], cnt);
}

__global__ void k_div(float* __restrict__ dout) {
    int t = blockIdx.x * blockDim.x + threadIdx.x;
    if (t >= NG * CH) return;
    dout[t] = g_pool[t] * (1.0f / fmaxf(g_cnt[t >> 6], 1.0f));
}

// ---------------- entry ------------------------------------------------------
extern "C" void kernel_launch(void* const* d_in, const int* in_sizes, int n_in,
                              void* d_out, int out_size) {
    const float* x     = (const float*)d_in[0];
    const void*  ei    = d_in[1];
    const void*  batch = d_in[2];
    const float* W1    = (const float*)d_in[3];
    const float* as1   = (const float*)d_in[4];
    const float* ad1   = (const float*)d_in[5];
    const float* b1    = (const float*)d_in[6];
    const float* W2    = (const float*)d_in[7];
    const float* as2   = (const float*)d_in[8];
    const float* ad2   = (const float*)d_in[9];
    const float* b2    = (const float*)d_in[10];
    float* dout = (float*)d_out;

    k_hist<<<(NE + 255) / 256, 256>>>(ei);
    k_scan_a<<<NB, 256>>>();
    k_scan_c<<<NB, 256>>>();
    k_scatter<<<(NEDG + 255) / 256, 256>>>(ei);

    // layer 1
    k_gemm<true><<<592, 256>>>((const float2*)x, W1, as1, ad1);
    k_agg<<<(NN * 32 + 255) / 256, 256>>>(b1);

    // layer 2 (input = g_out)
    k_gemm<false><<<592, 256>>>(nullptr, W2, as2, ad2);
    k_agg<<<(NN * 32 + 255) / 256, 256>>>(b2);

    // pool
    k_pool<<<(NGRP * 32 + 255) / 256, 256>>>(batch, ei);
    k_div<<<(NG * CH + 255) / 256, 256>>>(dout);
}